// round 14
// baseline (speedup 1.0000x reference)
#include <cuda_runtime.h>
#include <cuda_fp16.h>
#include <math.h>
#include <stdint.h>

// ---------------------------------------------------------------------------
// MoEGate (DeepSeek-V3 noaux_tc router) on GB300 sm_103a (compute_103 PTX)
// Round 14: round-13 pipeline made branchless (clamped stage/split indices ->
//           single basic block per tile so ptxas interleaves cp.async/split/
//           LDSM/HMMA), and the A-split remapped to 8 LDS.128 + 8 STS.128
//           per thread (was 8+16 with a dependent chain). Numerics identical:
//           fp16 2-way split, 3 products, hh/corr/master exact-2Sum @128k.
// ---------------------------------------------------------------------------

#define SEQ     16384
#define HIDDEN  7168
#define NEXP    256
#define NGROUP  8
#define TOPKG   4
#define TOPK    8
#define RSCALE  2.5f

#define KTILE   64
#define NTILES  (HIDDEN / KTILE)     // 112
#define NTHR    256

// ---- scratch -----
__device__ float g_scores[(size_t)SEQ * NEXP];
// B planes: [2][NTILES][256 cols][32 words]; row = 32 words, 8-granule swizzle
#define B_TILE_WORDS  (256 * 32)                       // 8192
#define B_PLANE_WORDS ((size_t)NTILES * B_TILE_WORDS)  // 917504
__device__ __align__(16) uint32_t g_Bsplit[2 * B_PLANE_WORDS];

// ---- smem layout (bytes) ----
// A32 raw fp32 (row-major 256B/row): 2 bufs x 32768 at 0
// A fp16 planes: 2 bufs x 32768 at 65536 (A0 +0, A1 +16384)
// B fp16 planes: 3 bufs x 32768 at 131072 (B0 +0, B1 +16384)
#define OFF_A32(b)  ((uint32_t)(b) * 32768u)
#define OFF_AP(b)   (65536u + (uint32_t)(b) * 32768u)
#define OFF_BP(b)   (131072u + (uint32_t)(b) * 32768u)
#define SMEM_BYTES  229376

// ------------------------------- helpers -----------------------------------
__device__ __forceinline__ uint16_t f16u(float x) {
    return __half_as_ushort(__float2half_rn(x));
}
__device__ __forceinline__ float f16f(uint16_t u) {
    return __half2float(__ushort_as_half(u));
}
__device__ __forceinline__ void split2(float x, uint16_t& s0, uint16_t& s1) {
    s0 = f16u(x);
    const float r = x - f16f(s0);       // exact (Sterbenz)
    s1 = f16u(r * 4096.0f);
}
__device__ __forceinline__ void mma16(float* d, const uint32_t* a,
                                      uint32_t b0, uint32_t b1) {
    asm("mma.sync.aligned.m16n8k16.row.col.f32.f16.f16.f32 "
        "{%0,%1,%2,%3}, {%4,%5,%6,%7}, {%8,%9}, {%0,%1,%2,%3};"
        : "+f"(d[0]), "+f"(d[1]), "+f"(d[2]), "+f"(d[3])
        : "r"(a[0]), "r"(a[1]), "r"(a[2]), "r"(a[3]), "r"(b0), "r"(b1));
}
#define LDSM4(r0, r1, r2, r3, addr)                                            \
    asm volatile("ldmatrix.sync.aligned.m8n8.x4.shared.b16 {%0,%1,%2,%3}, [%4];" \
        : "=r"(r0), "=r"(r1), "=r"(r2), "=r"(r3) : "r"(addr))
__device__ __forceinline__ void cp16(uint32_t dst, const void* src) {
    asm volatile("cp.async.cg.shared.global [%0], [%1], 16;" :: "r"(dst), "l"(src));
}
// exact 2Sum: master += hh; residual * 4096 accumulated into corr; hh = 0.
__device__ __forceinline__ void twosum_acc(float& master, float& corr, float& hh) {
    float a = master, b = hh, s, bp, ap, da, db, r;
    asm("add.rn.f32 %0, %1, %2;" : "=f"(s)  : "f"(a),  "f"(b));
    asm("sub.rn.f32 %0, %1, %2;" : "=f"(bp) : "f"(s),  "f"(a));
    asm("sub.rn.f32 %0, %1, %2;" : "=f"(ap) : "f"(s),  "f"(bp));
    asm("sub.rn.f32 %0, %1, %2;" : "=f"(db) : "f"(b),  "f"(bp));
    asm("sub.rn.f32 %0, %1, %2;" : "=f"(da) : "f"(a),  "f"(ap));
    asm("add.rn.f32 %0, %1, %2;" : "=f"(r)  : "f"(da), "f"(db));
    asm("fma.rn.f32 %0, %1, 0f45800000, %0;" : "+f"(corr) : "f"(r)); // corr += r*4096
    master = s;
    hh = 0.0f;
}

// ------------------------- W split (pre-swizzled planes) -------------------
// layout [t][col][32 words]; word w stored at w ^ ((col&7)<<2)
__global__ void wsplit_kernel(const float* __restrict__ W) {
    const int n = blockIdx.x;
    const int k = blockIdx.y * 256 + threadIdx.x;
    const float bp = W[(size_t)n * HIDDEN + k] * 64.0f;
    uint16_t s0, s1;
    split2(bp, s0, s1);
    const int t    = k >> 6;
    const int kk   = k & 63;
    const uint32_t word = (uint32_t)(kk >> 1) ^ (uint32_t)((n & 7) << 2);
    const int half = k & 1;
    const size_t wi = (size_t)t * B_TILE_WORDS + (size_t)n * 32 + word;
    uint16_t* base = (uint16_t*)g_Bsplit;
    base[(size_t)0 * B_PLANE_WORDS * 2 + wi * 2 + half] = s0;
    base[(size_t)1 * B_PLANE_WORDS * 2 + wi * 2 + half] = s1;
}

// ------------------------------- GEMM kernel -------------------------------
__global__ __launch_bounds__(NTHR, 1)
void gemm_fp16_kernel(const float* __restrict__ A) {
    extern __shared__ uint32_t sm[];
    char* smc = (char*)sm;
    const int tid  = threadIdx.x;
    const int wid  = tid >> 5;
    const int lane = tid & 31;
    const int n0   = blockIdx.x * 128;
    const int m0   = blockIdx.y * 128;

    uint32_t smAddr;
    asm("{ .reg .u64 t; cvta.to.shared.u64 t, %1; cvt.u32.u64 %0, t; }"
        : "=r"(smAddr) : "l"((const void*)sm));

    // ---- frag mappings: warp grid 4m x 2n, warp tile m32 x n64
    const int wm = wid & 3;
    const int wn = wid >> 2;

    // A ldmatrix lane addresses, relative to plane-pair base (A0).
    uint32_t offA[2][2];
    {
        const int R = wm * 32 + (lane & 7) + ((lane >> 3) & 1) * 8;
        const int gl = lane >> 4;
        #pragma unroll
        for (int p = 0; p < 2; p++)
            #pragma unroll
            for (int m = 0; m < 2; m++) {
                const int Rm = R + m * 16;
                offA[p][m] = (uint32_t)(p * 16384 + Rm * 128
                           + ((gl ^ (Rm & 7)) << 4));
            }
    }
    // B ldmatrix lane addresses, relative to B plane-pair base (B0).
    uint32_t offB[2][4];
    {
        const int gl = (lane >> 3) & 1;
        #pragma unroll
        for (int p = 0; p < 2; p++)
            #pragma unroll
            for (int q = 0; q < 4; q++) {
                const int C = wn * 64 + q * 16 + (lane >> 4) * 8 + (lane & 7);
                offB[p][q] = (uint32_t)(p * 16384 + C * 128
                           + ((gl ^ (C & 7)) << 4));
            }
    }

    float hh[16][4];
    float corr[16][4];
    float master[16][4];
    #pragma unroll
    for (int fi = 0; fi < 16; fi++)
        #pragma unroll
        for (int j = 0; j < 4; j++) {
            hh[fi][j] = 0.0f; corr[fi][j] = 0.0f; master[fi][j] = 0.0f;
        }

    // ---- staging: A raw fp32 row-major (256B/row) + B planes
    // thread owns (row sr = tid>>1, half sh = tid&1): 128 contiguous bytes
    const int sr = tid >> 1;
    const int sh = tid & 1;
    const float* aSrc0 = A + (size_t)(m0 + sr) * HIDDEN + sh * 32;
    const uint32_t aDstOff = (uint32_t)(sr * 256 + sh * 128);
    auto stage = [&](int t, int abuf, int bbuf) {
        const float* asrc = aSrc0 + (size_t)t * KTILE;
        const uint32_t adst = smAddr + OFF_A32(abuf) + aDstOff;
        #pragma unroll
        for (int j = 0; j < 8; j++)
            cp16(adst + (uint32_t)j * 16u, asrc + j * 4);
        #pragma unroll
        for (int p = 0; p < 2; p++) {
            const uint32_t* bsrc = g_Bsplit + (size_t)p * B_PLANE_WORDS
                                 + (size_t)t * B_TILE_WORDS + (size_t)n0 * 32 + tid * 16;
            const uint32_t bdst = smAddr + OFF_BP(bbuf) + (uint32_t)(p * 16384)
                                + (uint32_t)tid * 64u;
            cp16(bdst,      bsrc);      cp16(bdst + 16, bsrc + 4);
            cp16(bdst + 32, bsrc + 8);  cp16(bdst + 48, bsrc + 12);
        }
        asm volatile("cp.async.commit_group;");
    };

    // split A32(buf) -> fp16 planes(buf): 8 LDS.128 (batched) then per
    // granule-pair one STS.128 per plane. Conflict-free both directions.
    const uint32_t swr = (uint32_t)(sr & 7);
    auto splitA = [&](int buf) {
        const char* a32 = smc + OFF_A32(buf) + aDstOff;
        char* pl = smc + OFF_AP(buf);
        float4 v[8];
        #pragma unroll
        for (int j = 0; j < 8; j++)
            v[j] = *(const float4*)(a32 + j * 16);
        #pragma unroll
        for (int pr = 0; pr < 4; pr++) {           // granule pair
            uint16_t lo[8], hi[8];
            #pragma unroll
            for (int e = 0; e < 4; e++) {
                split2((&v[pr * 2].x)[e],     lo[e],     hi[e]);
                split2((&v[pr * 2 + 1].x)[e], lo[4 + e], hi[4 + e]);
            }
            uint4 p0, p1;
            p0.x = (uint32_t)lo[0] | ((uint32_t)lo[1] << 16);
            p0.y = (uint32_t)lo[2] | ((uint32_t)lo[3] << 16);
            p0.z = (uint32_t)lo[4] | ((uint32_t)lo[5] << 16);
            p0.w = (uint32_t)lo[6] | ((uint32_t)lo[7] << 16);
            p1.x = (uint32_t)hi[0] | ((uint32_t)hi[1] << 16);
            p1.y = (uint32_t)hi[2] | ((uint32_t)hi[3] << 16);
            p1.z = (uint32_t)hi[4] | ((uint32_t)hi[5] << 16);
            p1.w = (uint32_t)hi[6] | ((uint32_t)hi[7] << 16);
            const uint32_t jg = (uint32_t)(sh * 4 + pr);
            const uint32_t off = (uint32_t)(sr * 128) + ((jg ^ swr) << 4);
            *(uint4*)(pl + off)         = p0;
            *(uint4*)(pl + 16384 + off) = p1;
        }
    };

    // ---- prologue: 2 tiles in flight, split tile 0
    stage(0, 0, 0);
    stage(1, 1, 1);
    asm volatile("cp.async.wait_group 1;");   // tile 0 arrived
    __syncthreads();
    splitA(0);

    #pragma unroll 1
    for (int t = 0; t < NTILES; ++t) {
        asm volatile("cp.async.wait_group 0;");  // A32/B of t+1 arrived
        __syncthreads();                         // split(t) planes visible

        // Branchless: clamp staged tile; buffer indices keep disjointness.
        const int ts = (t + 2 < NTILES) ? (t + 2) : 0;
        stage(ts, (t + 2) & 1, (t + 2) % 3);     // overlaps mma(t)
        splitA((t + 1) & 1);                      // independent of mma(t)

        const uint32_t sbA = smAddr + OFF_AP(t & 1);
        const uint32_t sbB = smAddr + OFF_BP(t % 3);

        // ---- 4 k-steps (k16): ldmatrix frags + 3 products each
        #pragma unroll
        for (int ks = 0; ks < 4; ks++) {
            const uint32_t ksx = (uint32_t)(ks << 5);
            uint32_t Af[2][2][4];
            #pragma unroll
            for (int p = 0; p < 2; p++)
                #pragma unroll
                for (int m = 0; m < 2; m++)
                    LDSM4(Af[p][m][0], Af[p][m][1], Af[p][m][2], Af[p][m][3],
                          sbA + (offA[p][m] ^ ksx));
            #pragma unroll
            for (int q = 0; q < 4; q++) {
                uint32_t B0[4], B1[4];
                LDSM4(B0[0], B0[1], B0[2], B0[3], sbB + (offB[0][q] ^ ksx));
                LDSM4(B1[0], B1[1], B1[2], B1[3], sbB + (offB[1][q] ^ ksx));
                #pragma unroll
                for (int hf = 0; hf < 2; hf++) {
                    const int nf = q * 2 + hf;
                    const uint32_t b00 = B0[hf * 2], b01 = B0[hf * 2 + 1];
                    const uint32_t b10 = B1[hf * 2], b11 = B1[hf * 2 + 1];
                    #pragma unroll
                    for (int m = 0; m < 2; m++) {
                        const int fi = nf * 2 + m;
                        mma16(hh[fi],   Af[0][m], b00, b01); // a0*b0
                        mma16(corr[fi], Af[0][m], b10, b11); // a0*b1
                        mma16(corr[fi], Af[1][m], b00, b01); // a1*b0
                    }
                }
            }
        }

        // ---- exact drain hh -> master every 2 tiles (= every 128 k, 56x)
        if (t & 1) {
            #pragma unroll
            for (int fi = 0; fi < 16; fi++)
                #pragma unroll
                for (int j = 0; j < 4; j++)
                    twosum_acc(master[fi][j], corr[fi][j], hh[fi][j]);
        }
    }

    // ---- epilogue: fp64 combine (undo scales) + sigmoid, direct stores
    const int qq = lane >> 2;
    const int c  = lane & 3;
    #pragma unroll
    for (int fi = 0; fi < 16; fi++) {
        const int nf = fi >> 1;
        const int m  = fi & 1;
        const int r1 = m0 + wm * 32 + m * 16 + qq;
        const int r2 = r1 + 8;
        const int cc = n0 + wn * 64 + nf * 8 + c * 2;
        double lg[4];
        #pragma unroll
        for (int j = 0; j < 4; j++)
            lg[j] = ((double)master[fi][j]
                   + (double)corr[fi][j] * (1.0 / 4096.0)) * (1.0 / 64.0);
        float2 v1, v2;
        v1.x = (float)(1.0 / (1.0 + exp(-lg[0])));
        v1.y = (float)(1.0 / (1.0 + exp(-lg[1])));
        v2.x = (float)(1.0 / (1.0 + exp(-lg[2])));
        v2.y = (float)(1.0 / (1.0 + exp(-lg[3])));
        *(float2*)&g_scores[(size_t)r1 * NEXP + cc] = v1;
        *(float2*)&g_scores[(size_t)r2 * NEXP + cc] = v2;
    }
}

// ----------------------------- Top-k kernel --------------------------------
__global__ __launch_bounds__(256)
void topk_kernel(const float* __restrict__ bias,
                 float* __restrict__ out,
                 int write_idx)
{
    const int warp = threadIdx.x >> 5;
    const int lane = threadIdx.x & 31;
    const int row  = blockIdx.x * 8 + warp;
    if (row >= SEQ) return;

    const float* sp = g_scores + (size_t)row * NEXP + lane * 8;
    const float4 sA = *(const float4*)sp;
    const float4 sB = *(const float4*)(sp + 4);
    float sv[8] = {sA.x, sA.y, sA.z, sA.w, sB.x, sB.y, sB.z, sB.w};

    float c[8];
    #pragma unroll
    for (int i = 0; i < 8; i++)
        c[i] = sv[i] + __ldg(&bias[lane * 8 + i]);

    float m1 = -INFINITY, m2 = -INFINITY;
    #pragma unroll
    for (int i = 0; i < 8; i++) {
        if (c[i] > m1)      { m2 = m1; m1 = c[i]; }
        else if (c[i] > m2) { m2 = c[i]; }
    }
    #pragma unroll
    for (int off = 1; off <= 2; off <<= 1) {
        const float o1 = __shfl_xor_sync(0xFFFFFFFFu, m1, off);
        const float o2 = __shfl_xor_sync(0xFFFFFFFFu, m2, off);
        const float n1 = fmaxf(m1, o1);
        const float n2 = fmaxf(fminf(m1, o1), fmaxf(m2, o2));
        m1 = n1; m2 = n2;
    }
    const float gs = m1 + m2;
    const int   g  = lane >> 2;

    int rank = 0;
    #pragma unroll
    for (int hh = 0; hh < NGROUP; hh++) {
        const float gh = __shfl_sync(0xFFFFFFFFu, gs, hh * 4);
        rank += (gh > gs) || (gh == gs && hh < g);
    }
    const bool sel = (rank < TOPKG);

    float tmp[8];
    #pragma unroll
    for (int i = 0; i < 8; i++)
        tmp[i] = sel ? c[i] : 0.0f;

    float wsel[8];
    int   isel[8];
    float wsum = 0.0f;
    #pragma unroll
    for (int t = 0; t < TOPK; t++) {
        float bv = tmp[0];
        int   bi = 0;
        #pragma unroll
        for (int i = 1; i < 8; i++)
            if (tmp[i] > bv) { bv = tmp[i]; bi = i; }
        int   be   = lane * 8 + bi;
        float braw = sv[bi];
        #pragma unroll
        for (int off = 16; off; off >>= 1) {
            const float ov  = __shfl_xor_sync(0xFFFFFFFFu, bv, off);
            const int   oe  = __shfl_xor_sync(0xFFFFFFFFu, be, off);
            const float orw = __shfl_xor_sync(0xFFFFFFFFu, braw, off);
            if (ov > bv || (ov == bv && oe < be)) { bv = ov; be = oe; braw = orw; }
        }
        wsel[t] = braw;
        isel[t] = be;
        wsum += braw;
        if ((be >> 3) == lane) tmp[be & 7] = -INFINITY;
    }

    const float invd = RSCALE / (wsum + 1e-20f);
    if (lane == 0) {
        #pragma unroll
        for (int t = 0; t < TOPK; t++)
            out[(size_t)row * TOPK + t] = wsel[t] * invd;
        if (write_idx) {
            #pragma unroll
            for (int t = 0; t < TOPK; t++)
                out[(size_t)SEQ * TOPK + (size_t)row * TOPK + t] = (float)isel[t];
        }
    }
}

// ----------------------------- launch --------------------------------------
extern "C" void kernel_launch(void* const* d_in, const int* in_sizes, int n_in,
                              void* d_out, int out_size)
{
    const float* hidden = (const float*)d_in[0];
    const float* weight = (const float*)d_in[1];
    const float* bias   = (const float*)d_in[2];
    for (int i = 0; i < n_in; i++) {
        if (in_sizes[i] == SEQ * HIDDEN)       hidden = (const float*)d_in[i];
        else if (in_sizes[i] == NEXP * HIDDEN) weight = (const float*)d_in[i];
        else if (in_sizes[i] == NEXP)          bias   = (const float*)d_in[i];
    }
    float* out = (float*)d_out;

    cudaFuncSetAttribute(gemm_fp16_kernel,
                         cudaFuncAttributeMaxDynamicSharedMemorySize, SMEM_BYTES);

    wsplit_kernel<<<dim3(NEXP, HIDDEN / 256), 256>>>(weight);
    gemm_fp16_kernel<<<dim3(NEXP / 128, SEQ / 128), NTHR, SMEM_BYTES>>>(hidden);

    const int write_idx = (out_size >= 2 * SEQ * TOPK) ? 1 : 0;
    topk_kernel<<<SEQ / 8, 256>>>(bias, out, write_idx);
}

// round 15
// speedup vs baseline: 1.3475x; 1.3475x over previous
#include <cuda_runtime.h>
#include <cuda_fp16.h>
#include <math.h>
#include <stdint.h>

// ---------------------------------------------------------------------------
// MoEGate (DeepSeek-V3 noaux_tc router) on GB300 sm_103a (compute_103 PTX)
// Round 15: exact round-13 kernel (best: 1055us) with ONE change: the
//           stage/split calls are branchless (clamped tile index, buffers
//           provably disjoint in the tail) so the whole tile body is one
//           basic block and ptxas can interleave cp.async/split/LDSM/HMMA.
//           splitA kept in r13's low-register per-granule form (r14's
//           batched form spilled: +333us).
// ---------------------------------------------------------------------------

#define SEQ     16384
#define HIDDEN  7168
#define NEXP    256
#define NGROUP  8
#define TOPKG   4
#define TOPK    8
#define RSCALE  2.5f

#define KTILE   64
#define NTILES  (HIDDEN / KTILE)     // 112
#define NTHR    256

// ---- scratch -----
__device__ float g_scores[(size_t)SEQ * NEXP];
// B planes: [2][NTILES][256 cols][32 words]; row = 32 words, 8-granule swizzle
#define B_TILE_WORDS  (256 * 32)                       // 8192
#define B_PLANE_WORDS ((size_t)NTILES * B_TILE_WORDS)  // 917504
__device__ __align__(16) uint32_t g_Bsplit[2 * B_PLANE_WORDS];

// ---- smem layout (bytes) ----
// A32 raw fp32:   2 bufs x 32768   at 0
// A fp16 planes:  2 bufs x 32768   at 65536   (A0 +0, A1 +16384)
// B fp16 planes:  3 bufs x 32768   at 131072  (B0 +0, B1 +16384)
#define OFF_A32(b)  ((uint32_t)(b) * 32768u)
#define OFF_AP(b)   (65536u + (uint32_t)(b) * 32768u)
#define OFF_BP(b)   (131072u + (uint32_t)(b) * 32768u)
#define SMEM_BYTES  229376

// ------------------------------- helpers -----------------------------------
__device__ __forceinline__ uint16_t f16u(float x) {
    return __half_as_ushort(__float2half_rn(x));
}
__device__ __forceinline__ float f16f(uint16_t u) {
    return __half2float(__ushort_as_half(u));
}
__device__ __forceinline__ void split2(float x, uint16_t& s0, uint16_t& s1) {
    s0 = f16u(x);
    const float r = x - f16f(s0);       // exact (Sterbenz)
    s1 = f16u(r * 4096.0f);
}
__device__ __forceinline__ void mma16(float* d, const uint32_t* a,
                                      uint32_t b0, uint32_t b1) {
    asm("mma.sync.aligned.m16n8k16.row.col.f32.f16.f16.f32 "
        "{%0,%1,%2,%3}, {%4,%5,%6,%7}, {%8,%9}, {%0,%1,%2,%3};"
        : "+f"(d[0]), "+f"(d[1]), "+f"(d[2]), "+f"(d[3])
        : "r"(a[0]), "r"(a[1]), "r"(a[2]), "r"(a[3]), "r"(b0), "r"(b1));
}
#define LDSM4(r0, r1, r2, r3, addr)                                            \
    asm volatile("ldmatrix.sync.aligned.m8n8.x4.shared.b16 {%0,%1,%2,%3}, [%4];" \
        : "=r"(r0), "=r"(r1), "=r"(r2), "=r"(r3) : "r"(addr))
__device__ __forceinline__ void cp16(uint32_t dst, const void* src) {
    asm volatile("cp.async.cg.shared.global [%0], [%1], 16;" :: "r"(dst), "l"(src));
}
// exact 2Sum: master += hh; residual * 4096 accumulated into corr; hh = 0.
__device__ __forceinline__ void twosum_acc(float& master, float& corr, float& hh) {
    float a = master, b = hh, s, bp, ap, da, db, r;
    asm("add.rn.f32 %0, %1, %2;" : "=f"(s)  : "f"(a),  "f"(b));
    asm("sub.rn.f32 %0, %1, %2;" : "=f"(bp) : "f"(s),  "f"(a));
    asm("sub.rn.f32 %0, %1, %2;" : "=f"(ap) : "f"(s),  "f"(bp));
    asm("sub.rn.f32 %0, %1, %2;" : "=f"(db) : "f"(b),  "f"(bp));
    asm("sub.rn.f32 %0, %1, %2;" : "=f"(da) : "f"(a),  "f"(ap));
    asm("add.rn.f32 %0, %1, %2;" : "=f"(r)  : "f"(da), "f"(db));
    asm("fma.rn.f32 %0, %1, 0f45800000, %0;" : "+f"(corr) : "f"(r)); // corr += r*4096
    master = s;
    hh = 0.0f;
}

// ------------------------- W split (pre-swizzled planes) -------------------
// layout [t][col][32 words]; word w stored at w ^ ((col&7)<<2)
__global__ void wsplit_kernel(const float* __restrict__ W) {
    const int n = blockIdx.x;
    const int k = blockIdx.y * 256 + threadIdx.x;
    const float bp = W[(size_t)n * HIDDEN + k] * 64.0f;
    uint16_t s0, s1;
    split2(bp, s0, s1);
    const int t    = k >> 6;
    const int kk   = k & 63;
    const uint32_t word = (uint32_t)(kk >> 1) ^ (uint32_t)((n & 7) << 2);
    const int half = k & 1;
    const size_t wi = (size_t)t * B_TILE_WORDS + (size_t)n * 32 + word;
    uint16_t* base = (uint16_t*)g_Bsplit;
    base[(size_t)0 * B_PLANE_WORDS * 2 + wi * 2 + half] = s0;
    base[(size_t)1 * B_PLANE_WORDS * 2 + wi * 2 + half] = s1;
}

// ------------------------------- GEMM kernel -------------------------------
__global__ __launch_bounds__(NTHR, 1)
void gemm_fp16_kernel(const float* __restrict__ A) {
    extern __shared__ uint32_t sm[];
    char* smc = (char*)sm;
    const int tid  = threadIdx.x;
    const int wid  = tid >> 5;
    const int lane = tid & 31;
    const int n0   = blockIdx.x * 128;
    const int m0   = blockIdx.y * 128;

    uint32_t smAddr;
    asm("{ .reg .u64 t; cvta.to.shared.u64 t, %1; cvt.u32.u64 %0, t; }"
        : "=r"(smAddr) : "l"((const void*)sm));

    // ---- frag mappings: warp grid 4m x 2n, warp tile m32 x n64
    const int wm = wid & 3;
    const int wn = wid >> 2;

    // A ldmatrix lane addresses, relative to plane-pair base (A0).
    uint32_t offA[2][2];
    {
        const int R = wm * 32 + (lane & 7) + ((lane >> 3) & 1) * 8;
        const int gl = lane >> 4;
        #pragma unroll
        for (int p = 0; p < 2; p++)
            #pragma unroll
            for (int m = 0; m < 2; m++) {
                const int Rm = R + m * 16;
                offA[p][m] = (uint32_t)(p * 16384 + Rm * 128
                           + ((gl ^ (Rm & 7)) << 4));
            }
    }
    // B ldmatrix lane addresses, relative to B plane-pair base (B0).
    uint32_t offB[2][4];
    {
        const int gl = (lane >> 3) & 1;
        #pragma unroll
        for (int p = 0; p < 2; p++)
            #pragma unroll
            for (int q = 0; q < 4; q++) {
                const int C = wn * 64 + q * 16 + (lane >> 4) * 8 + (lane & 7);
                offB[p][q] = (uint32_t)(p * 16384 + C * 128
                           + ((gl ^ (C & 7)) << 4));
            }
    }

    float hh[16][4];
    float corr[16][4];
    float master[16][4];
    #pragma unroll
    for (int fi = 0; fi < 16; fi++)
        #pragma unroll
        for (int j = 0; j < 4; j++) {
            hh[fi][j] = 0.0f; corr[fi][j] = 0.0f; master[fi][j] = 0.0f;
        }

    // ---- staging: A raw fp32 flat granules + B planes, one commit group
    // A: granule gi = tid + 256j; row = gi>>4, col-granule = gi&15
    const int sr  = tid >> 4;          // base row (increments by 16 per j)
    const int scg = tid & 15;          // col granule (16B = 4 fp32)
    const float* aSrc0 = A + (size_t)(m0 + sr) * HIDDEN + scg * 4;
    auto stage = [&](int t, int abuf, int bbuf) {
        const float* asrc = aSrc0 + (size_t)t * KTILE;
        const uint32_t adst = smAddr + OFF_A32(abuf) + (uint32_t)tid * 16u;
        #pragma unroll
        for (int j = 0; j < 8; j++)
            cp16(adst + (uint32_t)j * 4096u, asrc + (size_t)j * 16 * HIDDEN);
        #pragma unroll
        for (int p = 0; p < 2; p++) {
            const uint32_t* bsrc = g_Bsplit + (size_t)p * B_PLANE_WORDS
                                 + (size_t)t * B_TILE_WORDS + (size_t)n0 * 32 + tid * 16;
            const uint32_t bdst = smAddr + OFF_BP(bbuf) + (uint32_t)(p * 16384)
                                + (uint32_t)tid * 64u;
            cp16(bdst,      bsrc);      cp16(bdst + 16, bsrc + 4);
            cp16(bdst + 32, bsrc + 8);  cp16(bdst + 48, bsrc + 12);
        }
        asm volatile("cp.async.commit_group;");
    };

    // split A32(buf) -> fp16 planes(buf); conflict-free LDS.128 / STS.64
    const uint32_t swr = (uint32_t)(sr & 7);           // j-invariant
    const uint32_t spOff0 = (uint32_t)(sr * 128)
                          + ((((uint32_t)scg >> 1) ^ swr) << 4)
                          + ((uint32_t)scg & 1u) * 8u;
    auto splitA = [&](int buf) {
        const char* a32 = smc + OFF_A32(buf);
        char* pl = smc + OFF_AP(buf);
        #pragma unroll
        for (int j = 0; j < 8; j++) {
            const float4 v = *(const float4*)(a32 + (size_t)tid * 16 + (size_t)j * 4096);
            uint16_t x0, x1, y0, y1, z0, z1, w0, w1;
            split2(v.x, x0, x1);
            split2(v.y, y0, y1);
            split2(v.z, z0, z1);
            split2(v.w, w0, w1);
            uint2 p0, p1;
            p0.x = (uint32_t)x0 | ((uint32_t)y0 << 16);
            p0.y = (uint32_t)z0 | ((uint32_t)w0 << 16);
            p1.x = (uint32_t)x1 | ((uint32_t)y1 << 16);
            p1.y = (uint32_t)z1 | ((uint32_t)w1 << 16);
            const uint32_t off = spOff0 + (uint32_t)j * 2048u;
            *(uint2*)(pl + off)         = p0;
            *(uint2*)(pl + 16384 + off) = p1;
        }
    };

    // ---- prologue: 2 tiles in flight, split tile 0
    stage(0, 0, 0);
    stage(1, 1, 1);
    asm volatile("cp.async.wait_group 1;");   // tile 0 arrived
    __syncthreads();
    splitA(0);

    #pragma unroll 1
    for (int t = 0; t < NTILES; ++t) {
        asm volatile("cp.async.wait_group 0;");  // A32/B of t+1 arrived
        __syncthreads();                         // split(t) planes visible

        // Branchless: clamp staged tile index; tail writes land in buffers
        // nobody reads (A32 (t+2)&1 vs split-read (t+1)&1; planes (t+1)&1 vs
        // mma-read t&1; B (t+2)%3 vs mma-read t%3 — all disjoint).
        const int ts = (t + 2 < NTILES) ? (t + 2) : 0;
        stage(ts, (t + 2) & 1, (t + 2) % 3);     // overlaps mma(t)
        splitA((t + 1) & 1);                      // independent of mma(t)

        const uint32_t sbA = smAddr + OFF_AP(t & 1);
        const uint32_t sbB = smAddr + OFF_BP(t % 3);

        // ---- 4 k-steps (k16): ldmatrix frags + 3 products each
        #pragma unroll
        for (int ks = 0; ks < 4; ks++) {
            const uint32_t ksx = (uint32_t)(ks << 5);
            uint32_t Af[2][2][4];
            #pragma unroll
            for (int p = 0; p < 2; p++)
                #pragma unroll
                for (int m = 0; m < 2; m++)
                    LDSM4(Af[p][m][0], Af[p][m][1], Af[p][m][2], Af[p][m][3],
                          sbA + (offA[p][m] ^ ksx));
            #pragma unroll
            for (int q = 0; q < 4; q++) {
                uint32_t B0[4], B1[4];
                LDSM4(B0[0], B0[1], B0[2], B0[3], sbB + (offB[0][q] ^ ksx));
                LDSM4(B1[0], B1[1], B1[2], B1[3], sbB + (offB[1][q] ^ ksx));
                #pragma unroll
                for (int hf = 0; hf < 2; hf++) {
                    const int nf = q * 2 + hf;
                    const uint32_t b00 = B0[hf * 2], b01 = B0[hf * 2 + 1];
                    const uint32_t b10 = B1[hf * 2], b11 = B1[hf * 2 + 1];
                    #pragma unroll
                    for (int m = 0; m < 2; m++) {
                        const int fi = nf * 2 + m;
                        mma16(hh[fi],   Af[0][m], b00, b01); // a0*b0
                        mma16(corr[fi], Af[0][m], b10, b11); // a0*b1
                        mma16(corr[fi], Af[1][m], b00, b01); // a1*b0
                    }
                }
            }
        }

        // ---- exact drain hh -> master every 2 tiles (= every 128 k, 56x)
        if (t & 1) {
            #pragma unroll
            for (int fi = 0; fi < 16; fi++)
                #pragma unroll
                for (int j = 0; j < 4; j++)
                    twosum_acc(master[fi][j], corr[fi][j], hh[fi][j]);
        }
    }

    // ---- epilogue: fp64 combine (undo scales) + sigmoid, direct stores
    const int qq = lane >> 2;
    const int c  = lane & 3;
    #pragma unroll
    for (int fi = 0; fi < 16; fi++) {
        const int nf = fi >> 1;
        const int m  = fi & 1;
        const int r1 = m0 + wm * 32 + m * 16 + qq;
        const int r2 = r1 + 8;
        const int cc = n0 + wn * 64 + nf * 8 + c * 2;
        double lg[4];
        #pragma unroll
        for (int j = 0; j < 4; j++)
            lg[j] = ((double)master[fi][j]
                   + (double)corr[fi][j] * (1.0 / 4096.0)) * (1.0 / 64.0);
        float2 v1, v2;
        v1.x = (float)(1.0 / (1.0 + exp(-lg[0])));
        v1.y = (float)(1.0 / (1.0 + exp(-lg[1])));
        v2.x = (float)(1.0 / (1.0 + exp(-lg[2])));
        v2.y = (float)(1.0 / (1.0 + exp(-lg[3])));
        *(float2*)&g_scores[(size_t)r1 * NEXP + cc] = v1;
        *(float2*)&g_scores[(size_t)r2 * NEXP + cc] = v2;
    }
}

// ----------------------------- Top-k kernel --------------------------------
__global__ __launch_bounds__(256)
void topk_kernel(const float* __restrict__ bias,
                 float* __restrict__ out,
                 int write_idx)
{
    const int warp = threadIdx.x >> 5;
    const int lane = threadIdx.x & 31;
    const int row  = blockIdx.x * 8 + warp;
    if (row >= SEQ) return;

    const float* sp = g_scores + (size_t)row * NEXP + lane * 8;
    const float4 sA = *(const float4*)sp;
    const float4 sB = *(const float4*)(sp + 4);
    float sv[8] = {sA.x, sA.y, sA.z, sA.w, sB.x, sB.y, sB.z, sB.w};

    float c[8];
    #pragma unroll
    for (int i = 0; i < 8; i++)
        c[i] = sv[i] + __ldg(&bias[lane * 8 + i]);

    float m1 = -INFINITY, m2 = -INFINITY;
    #pragma unroll
    for (int i = 0; i < 8; i++) {
        if (c[i] > m1)      { m2 = m1; m1 = c[i]; }
        else if (c[i] > m2) { m2 = c[i]; }
    }
    #pragma unroll
    for (int off = 1; off <= 2; off <<= 1) {
        const float o1 = __shfl_xor_sync(0xFFFFFFFFu, m1, off);
        const float o2 = __shfl_xor_sync(0xFFFFFFFFu, m2, off);
        const float n1 = fmaxf(m1, o1);
        const float n2 = fmaxf(fminf(m1, o1), fmaxf(m2, o2));
        m1 = n1; m2 = n2;
    }
    const float gs = m1 + m2;
    const int   g  = lane >> 2;

    int rank = 0;
    #pragma unroll
    for (int hh = 0; hh < NGROUP; hh++) {
        const float gh = __shfl_sync(0xFFFFFFFFu, gs, hh * 4);
        rank += (gh > gs) || (gh == gs && hh < g);
    }
    const bool sel = (rank < TOPKG);

    float tmp[8];
    #pragma unroll
    for (int i = 0; i < 8; i++)
        tmp[i] = sel ? c[i] : 0.0f;

    float wsel[8];
    int   isel[8];
    float wsum = 0.0f;
    #pragma unroll
    for (int t = 0; t < TOPK; t++) {
        float bv = tmp[0];
        int   bi = 0;
        #pragma unroll
        for (int i = 1; i < 8; i++)
            if (tmp[i] > bv) { bv = tmp[i]; bi = i; }
        int   be   = lane * 8 + bi;
        float braw = sv[bi];
        #pragma unroll
        for (int off = 16; off; off >>= 1) {
            const float ov  = __shfl_xor_sync(0xFFFFFFFFu, bv, off);
            const int   oe  = __shfl_xor_sync(0xFFFFFFFFu, be, off);
            const float orw = __shfl_xor_sync(0xFFFFFFFFu, braw, off);
            if (ov > bv || (ov == bv && oe < be)) { bv = ov; be = oe; braw = orw; }
        }
        wsel[t] = braw;
        isel[t] = be;
        wsum += braw;
        if ((be >> 3) == lane) tmp[be & 7] = -INFINITY;
    }

    const float invd = RSCALE / (wsum + 1e-20f);
    if (lane == 0) {
        #pragma unroll
        for (int t = 0; t < TOPK; t++)
            out[(size_t)row * TOPK + t] = wsel[t] * invd;
        if (write_idx) {
            #pragma unroll
            for (int t = 0; t < TOPK; t++)
                out[(size_t)SEQ * TOPK + (size_t)row * TOPK + t] = (float)isel[t];
        }
    }
}

// ----------------------------- launch --------------------------------------
extern "C" void kernel_launch(void* const* d_in, const int* in_sizes, int n_in,
                              void* d_out, int out_size)
{
    const float* hidden = (const float*)d_in[0];
    const float* weight = (const float*)d_in[1];
    const float* bias   = (const float*)d_in[2];
    for (int i = 0; i < n_in; i++) {
        if (in_sizes[i] == SEQ * HIDDEN)       hidden = (const float*)d_in[i];
        else if (in_sizes[i] == NEXP * HIDDEN) weight = (const float*)d_in[i];
        else if (in_sizes[i] == NEXP)          bias   = (const float*)d_in[i];
    }
    float* out = (float*)d_out;

    cudaFuncSetAttribute(gemm_fp16_kernel,
                         cudaFuncAttributeMaxDynamicSharedMemorySize, SMEM_BYTES);

    wsplit_kernel<<<dim3(NEXP, HIDDEN / 256), 256>>>(weight);
    gemm_fp16_kernel<<<dim3(NEXP / 128, SEQ / 128), NTHR, SMEM_BYTES>>>(hidden);

    const int write_idx = (out_size >= 2 * SEQ * TOPK) ? 1 : 0;
    topk_kernel<<<SEQ / 8, 256>>>(bias, out, write_idx);
}